// round 1
// baseline (speedup 1.0000x reference)
#include <cuda_runtime.h>
#include <cstdint>

#define BATCH 4
#define CH    256
#define NSEQ  4096
#define CTR   256

// Scratch (allocation-free rule: __device__ globals)
__device__ float g_q[BATCH * CTR * NSEQ];                 // [b][ct][n]
__device__ float g_k[BATCH * CTR * NSEQ];                 // [b][ct][n]
__device__ float g_v[BATCH * CTR * NSEQ];                 // [b][ct][n]
__device__ float g_ctx[BATCH * CTR * NSEQ];               // [b][ct][n]
__device__ float g_sim[(size_t)BATCH * NSEQ * NSEQ];      // [b][n][m]

#define BM 128
#define BN 128
#define BK 16

__device__ __forceinline__ uint32_t f2tf(float x) {
    uint32_t r;
    asm("cvt.rna.tf32.f32 %0, %1;" : "=r"(r) : "f"(x));
    return r;
}

__device__ __forceinline__ void mma8(float* c, const uint32_t* a, const uint32_t* b) {
    asm("mma.sync.aligned.m16n8k8.row.col.f32.tf32.tf32.f32 "
        "{%0,%1,%2,%3}, {%4,%5,%6,%7}, {%8,%9}, {%0,%1,%2,%3};"
        : "+f"(c[0]), "+f"(c[1]), "+f"(c[2]), "+f"(c[3])
        : "r"(a[0]), "r"(a[1]), "r"(a[2]), "r"(a[3]), "r"(b[0]), "r"(b[1]));
}

// Unified TN GEMM:  C[m,n] (+)= alpha * sum_k A(k,m) * B(k,n)
// AMODE 0: A(k,m) = A[k*lda + m]   (K-major)
// AMODE 1: A(k,m) = A[m*lda + k]   (row-major M x K)
// BMODE 0: B(k,n) = B[k*ldb + n]   (K-major)
// BMODE 1: B(k,n) = B[n*ldb + k]   (row-major N x K)
// Grid: (N/BN, M/BM, batch). All dims assumed divisible (true for this problem).
template <int AMODE, int BMODE, bool ACC>
__global__ void __launch_bounds__(256, 2) gemm_tn(
    const float* __restrict__ A, const float* __restrict__ Bg,
    float* __restrict__ Cg,
    int K, int lda, int ldb, int ldc,
    long long strideA, long long strideB, long long strideC,
    float alpha)
{
    __shared__ uint32_t As[BK][BM + 4];
    __shared__ uint32_t Bs[BK][BN + 4];

    const int tid = threadIdx.x;
    const int m0 = blockIdx.y * BM;
    const int n0 = blockIdx.x * BN;
    A  += (size_t)((long long)blockIdx.z * strideA);
    Bg += (size_t)((long long)blockIdx.z * strideB);
    Cg += (size_t)((long long)blockIdx.z * strideC);

    const int warp = tid >> 5;
    const int lane = tid & 31;
    const int wm = warp & 1;      // 2 warps along M: 64 rows each
    const int wn = warp >> 1;     // 4 warps along N: 32 cols each
    const int gid = lane >> 2;    // 0..7
    const int tig = lane & 3;     // 0..3

    float c[4][4][4];
    #pragma unroll
    for (int i = 0; i < 4; ++i)
        #pragma unroll
        for (int j = 0; j < 4; ++j)
            #pragma unroll
            for (int l = 0; l < 4; ++l) c[i][j][l] = 0.0f;

    // loader thread mappings
    const int km_k = tid >> 5;          // 0..7   (K-major modes)
    const int km_m = (tid & 31) << 2;   // 0..124
    const int tr_m = tid >> 1;          // 0..127 (transpose modes)
    const int tr_k = (tid & 1) << 3;    // 0 or 8

    float4 ra0, ra1, rb0, rb1;

    auto loadA = [&](int k0) {
        if (AMODE == 0) {
            const float* p = A + (size_t)(k0 + km_k) * lda + (m0 + km_m);
            ra0 = *(const float4*)p;
            ra1 = *(const float4*)(p + (size_t)8 * lda);
        } else {
            const float* p = A + (size_t)(m0 + tr_m) * lda + (k0 + tr_k);
            ra0 = *(const float4*)p;
            ra1 = *(const float4*)(p + 4);
        }
    };
    auto loadB = [&](int k0) {
        if (BMODE == 0) {
            const float* p = Bg + (size_t)(k0 + km_k) * ldb + (n0 + km_m);
            rb0 = *(const float4*)p;
            rb1 = *(const float4*)(p + (size_t)8 * ldb);
        } else {
            const float* p = Bg + (size_t)(n0 + tr_m) * ldb + (k0 + tr_k);
            rb0 = *(const float4*)p;
            rb1 = *(const float4*)(p + 4);
        }
    };
    auto storeA = [&]() {
        if (AMODE == 0) {
            As[km_k][km_m + 0] = f2tf(ra0.x); As[km_k][km_m + 1] = f2tf(ra0.y);
            As[km_k][km_m + 2] = f2tf(ra0.z); As[km_k][km_m + 3] = f2tf(ra0.w);
            As[km_k + 8][km_m + 0] = f2tf(ra1.x); As[km_k + 8][km_m + 1] = f2tf(ra1.y);
            As[km_k + 8][km_m + 2] = f2tf(ra1.z); As[km_k + 8][km_m + 3] = f2tf(ra1.w);
        } else {
            As[tr_k + 0][tr_m] = f2tf(ra0.x);
            As[tr_k + 1][tr_m] = f2tf(ra0.y);
            As[tr_k + 2][tr_m] = f2tf(ra0.z);
            As[tr_k + 3][tr_m] = f2tf(ra0.w);
            As[tr_k + 4][tr_m] = f2tf(ra1.x);
            As[tr_k + 5][tr_m] = f2tf(ra1.y);
            As[tr_k + 6][tr_m] = f2tf(ra1.z);
            As[tr_k + 7][tr_m] = f2tf(ra1.w);
        }
    };
    auto storeB = [&]() {
        if (BMODE == 0) {
            Bs[km_k][km_m + 0] = f2tf(rb0.x); Bs[km_k][km_m + 1] = f2tf(rb0.y);
            Bs[km_k][km_m + 2] = f2tf(rb0.z); Bs[km_k][km_m + 3] = f2tf(rb0.w);
            Bs[km_k + 8][km_m + 0] = f2tf(rb1.x); Bs[km_k + 8][km_m + 1] = f2tf(rb1.y);
            Bs[km_k + 8][km_m + 2] = f2tf(rb1.z); Bs[km_k + 8][km_m + 3] = f2tf(rb1.w);
        } else {
            Bs[tr_k + 0][tr_m] = f2tf(rb0.x);
            Bs[tr_k + 1][tr_m] = f2tf(rb0.y);
            Bs[tr_k + 2][tr_m] = f2tf(rb0.z);
            Bs[tr_k + 3][tr_m] = f2tf(rb0.w);
            Bs[tr_k + 4][tr_m] = f2tf(rb1.x);
            Bs[tr_k + 5][tr_m] = f2tf(rb1.y);
            Bs[tr_k + 6][tr_m] = f2tf(rb1.z);
            Bs[tr_k + 7][tr_m] = f2tf(rb1.w);
        }
    };

    const int ktiles = K / BK;
    loadA(0); loadB(0);

    for (int kt = 0; kt < ktiles; ++kt) {
        storeA(); storeB();
        __syncthreads();
        if (kt + 1 < ktiles) { loadA((kt + 1) * BK); loadB((kt + 1) * BK); }

        #pragma unroll
        for (int kk = 0; kk < BK; kk += 8) {
            uint32_t af[4][4], bf[4][2];
            #pragma unroll
            for (int mi = 0; mi < 4; ++mi) {
                const int mr = wm * 64 + mi * 16 + gid;
                af[mi][0] = As[kk + tig][mr];
                af[mi][1] = As[kk + tig][mr + 8];
                af[mi][2] = As[kk + tig + 4][mr];
                af[mi][3] = As[kk + tig + 4][mr + 8];
            }
            #pragma unroll
            for (int ni = 0; ni < 4; ++ni) {
                const int nc = wn * 32 + ni * 8 + gid;
                bf[ni][0] = Bs[kk + tig][nc];
                bf[ni][1] = Bs[kk + tig + 4][nc];
            }
            #pragma unroll
            for (int mi = 0; mi < 4; ++mi)
                #pragma unroll
                for (int ni = 0; ni < 4; ++ni)
                    mma8(c[mi][ni], af[mi], bf[ni]);
        }
        __syncthreads();
    }

    // Epilogue
    #pragma unroll
    for (int mi = 0; mi < 4; ++mi) {
        const int row = m0 + wm * 64 + mi * 16 + gid;
        #pragma unroll
        for (int ni = 0; ni < 4; ++ni) {
            const int col = n0 + wn * 32 + ni * 8 + tig * 2;
            float* p0 = Cg + (size_t)row * ldc + col;
            float* p1 = p0 + (size_t)8 * ldc;
            float2 u0 = make_float2(alpha * c[mi][ni][0], alpha * c[mi][ni][1]);
            float2 u1 = make_float2(alpha * c[mi][ni][2], alpha * c[mi][ni][3]);
            if (ACC) {
                float2 e0 = *(float2*)p0, e1 = *(float2*)p1;
                u0.x += e0.x; u0.y += e0.y;
                u1.x += e1.x; u1.y += e1.y;
            }
            *(float2*)p0 = u0;
            *(float2*)p1 = u1;
        }
    }
}

// Row softmax over the contiguous last dim of g_sim, in place.
// Grid: (NSEQ, BATCH), 256 threads; each row is 4096 floats = 1024 float4.
__global__ void __launch_bounds__(256) softmax_rows(float* __restrict__ S) {
    __shared__ float smax[8];
    __shared__ float ssum[8];
    const size_t rowoff = ((size_t)blockIdx.y * NSEQ + blockIdx.x) * NSEQ;
    float4* row = (float4*)(S + rowoff);
    const int t = threadIdx.x;

    float4 v[4];
    float mx = -3.0e38f;
    #pragma unroll
    for (int i = 0; i < 4; ++i) {
        v[i] = row[t + i * 256];
        mx = fmaxf(mx, fmaxf(fmaxf(v[i].x, v[i].y), fmaxf(v[i].z, v[i].w)));
    }
    #pragma unroll
    for (int o = 16; o > 0; o >>= 1) mx = fmaxf(mx, __shfl_xor_sync(0xffffffffu, mx, o));
    if ((t & 31) == 0) smax[t >> 5] = mx;
    __syncthreads();
    float bm = smax[0];
    #pragma unroll
    for (int w = 1; w < 8; ++w) bm = fmaxf(bm, smax[w]);

    float sum = 0.0f;
    #pragma unroll
    for (int i = 0; i < 4; ++i) {
        v[i].x = __expf(v[i].x - bm);
        v[i].y = __expf(v[i].y - bm);
        v[i].z = __expf(v[i].z - bm);
        v[i].w = __expf(v[i].w - bm);
        sum += v[i].x + v[i].y + v[i].z + v[i].w;
    }
    #pragma unroll
    for (int o = 16; o > 0; o >>= 1) sum += __shfl_xor_sync(0xffffffffu, sum, o);
    if ((t & 31) == 0) ssum[t >> 5] = sum;
    __syncthreads();
    float tot = 0.0f;
    #pragma unroll
    for (int w = 0; w < 8; ++w) tot += ssum[w];
    const float inv = 1.0f / tot;

    #pragma unroll
    for (int i = 0; i < 4; ++i) {
        v[i].x *= inv; v[i].y *= inv; v[i].z *= inv; v[i].w *= inv;
        row[t + i * 256] = v[i];
    }
}

extern "C" void kernel_launch(void* const* d_in, const int* in_sizes, int n_in,
                              void* d_out, int out_size) {
    const float* x  = (const float*)d_in[0];   // (B, C, N)
    const float* Wq = (const float*)d_in[1];   // (CT, C)
    const float* Wk = (const float*)d_in[2];   // (CT, C)
    const float* Wv = (const float*)d_in[3];   // (CT, C)
    const float* Wo = (const float*)d_in[4];   // (C, 2*CT)
    float* out = (float*)d_out;                // (B, C, N)
    (void)in_sizes; (void)n_in; (void)out_size;

    float *qp, *kp, *vp, *cp, *sp;
    cudaGetSymbolAddress((void**)&qp, g_q);
    cudaGetSymbolAddress((void**)&kp, g_k);
    cudaGetSymbolAddress((void**)&vp, g_v);
    cudaGetSymbolAddress((void**)&cp, g_ctx);
    cudaGetSymbolAddress((void**)&sp, g_sim);

    const dim3 blk(256);
    const long long PS = (long long)CTR * NSEQ;   // q/k/v/ctx batch stride
    const long long XS = (long long)CH * NSEQ;    // x / out batch stride
    const long long SS = (long long)NSEQ * NSEQ;  // sim batch stride

    // q/k/v[b][o][n] = sum_c W[o][c] * x[b][c][n]
    const dim3 gproj(NSEQ / BN, CTR / BM, BATCH);
    gemm_tn<1, 0, false><<<gproj, blk>>>(Wq, x, qp, CH, CH, NSEQ, NSEQ, 0, XS, PS, 1.0f);
    gemm_tn<1, 0, false><<<gproj, blk>>>(Wk, x, kp, CH, CH, NSEQ, NSEQ, 0, XS, PS, 1.0f);
    gemm_tn<1, 0, false><<<gproj, blk>>>(Wv, x, vp, CH, CH, NSEQ, NSEQ, 0, XS, PS, 1.0f);

    // sim[b][n][m] = (1/16) * sum_o q[b][o][n] * k[b][o][m]
    const dim3 gsim(NSEQ / BN, NSEQ / BM, BATCH);
    gemm_tn<0, 0, false><<<gsim, blk>>>(qp, kp, sp, CTR, NSEQ, NSEQ, NSEQ, PS, PS, SS, 0.0625f);

    // softmax over m (contiguous), in place
    const dim3 gsm(NSEQ, BATCH);
    softmax_rows<<<gsm, blk>>>(sp);

    // ctx[b][c][n] = sum_m v[b][c][m] * attn[b][n][m]
    const dim3 gctx(NSEQ / BN, CTR / BM, BATCH);
    gemm_tn<1, 1, false><<<gctx, blk>>>(vp, sp, cp, NSEQ, NSEQ, NSEQ, NSEQ, PS, SS, PS, 1.0f);

    // out[b][o][n] = sum_c Wo[o][c]*ctx[b][c][n] + sum_c Wo[o][CT+c]*x[b][c][n]
    const dim3 gout(NSEQ / BN, CH / BM, BATCH);
    gemm_tn<1, 0, false><<<gout, blk>>>(Wo,       cp, out, CTR, 2 * CTR, NSEQ, NSEQ, 0, PS, XS, 1.0f);
    gemm_tn<1, 0, true ><<<gout, blk>>>(Wo + CTR, x,  out, CH,  2 * CTR, NSEQ, NSEQ, 0, XS, XS, 1.0f);
}

// round 2
// speedup vs baseline: 1.1176x; 1.1176x over previous
#include <cuda_runtime.h>
#include <cstdint>

#define BATCH 4
#define CH    256
#define NSEQ  4096
#define CTR   256

// Scratch (allocation-free rule: __device__ globals)
__device__ float g_xt[BATCH * NSEQ * CH];                 // [b][n][c]
__device__ float g_q [BATCH * NSEQ * CTR];                // [b][n][ct]
__device__ float g_k [BATCH * NSEQ * CTR];                // [b][n][ct]
__device__ float g_v [BATCH * CTR * NSEQ];                // [b][ct][n]
__device__ float g_ctx[BATCH * NSEQ * CTR];               // [b][n][ct]
__device__ float g_sim[(size_t)BATCH * NSEQ * NSEQ];      // [b][n][m]

#define BM 128
#define BN 128
#define BK 16
#define PITCH 20   // floats per smem row (16 used + 4 pad) -> conflict-free LDSM

__device__ __forceinline__ uint32_t f2tf(float x) {
    uint32_t r;
    asm("cvt.rna.tf32.f32 %0, %1;" : "=r"(r) : "f"(x));
    return r;
}
__device__ __forceinline__ uint4 tf4(float4 v) {
    uint4 r;
    r.x = f2tf(v.x); r.y = f2tf(v.y); r.z = f2tf(v.z); r.w = f2tf(v.w);
    return r;
}
__device__ __forceinline__ uint32_t s2u(const void* p) {
    return (uint32_t)__cvta_generic_to_shared(p);
}
__device__ __forceinline__ void mma8(float* c, const uint32_t* a, const uint32_t* b) {
    asm("mma.sync.aligned.m16n8k8.row.col.f32.tf32.tf32.f32 "
        "{%0,%1,%2,%3}, {%4,%5,%6,%7}, {%8,%9}, {%0,%1,%2,%3};"
        : "+f"(c[0]), "+f"(c[1]), "+f"(c[2]), "+f"(c[3])
        : "r"(a[0]), "r"(a[1]), "r"(a[2]), "r"(a[3]), "r"(b[0]), "r"(b[1]));
}
__device__ __forceinline__ void ldsm4(uint32_t* r, uint32_t addr) {
    asm volatile("ldmatrix.sync.aligned.m8n8.x4.shared.b16 {%0,%1,%2,%3}, [%4];"
                 : "=r"(r[0]), "=r"(r[1]), "=r"(r[2]), "=r"(r[3]) : "r"(addr));
}
__device__ __forceinline__ void ldsm2(uint32_t* r, uint32_t addr) {
    asm volatile("ldmatrix.sync.aligned.m8n8.x2.shared.b16 {%0,%1}, [%2];"
                 : "=r"(r[0]), "=r"(r[1]) : "r"(addr));
}

// Row-major x row-major(T) GEMM: C[m,n] (+)= alpha * sum_k A[m][k] * B[n][k]
// A: M x K row-major (lda = row pitch), B: N x K row-major (ldb = row pitch).
// Grid: (N/BN, M/BM, batch), 256 threads. All dims divisible.
template <bool ACC>
__global__ void __launch_bounds__(256, 2) gemm_rr(
    const float* __restrict__ A, const float* __restrict__ Bg,
    float* __restrict__ Cg,
    int K, int lda, int ldb, int ldc,
    long long strideA, long long strideB, long long strideC,
    float alpha)
{
    __shared__ uint32_t As[BM * PITCH];
    __shared__ uint32_t Bs[BN * PITCH];

    const int tid = threadIdx.x;
    const int m0 = blockIdx.y * BM;
    const int n0 = blockIdx.x * BN;
    A  += (size_t)((long long)blockIdx.z * strideA);
    Bg += (size_t)((long long)blockIdx.z * strideB);
    Cg += (size_t)((long long)blockIdx.z * strideC);

    const int warp = tid >> 5;
    const int lane = tid & 31;
    const int wm = warp & 1;      // 2 warps along M: 64 rows each
    const int wn = warp >> 1;     // 4 warps along N: 32 cols each
    const int gid = lane >> 2;
    const int tig = lane & 3;

    float c[4][4][4];
    #pragma unroll
    for (int i = 0; i < 4; ++i)
        #pragma unroll
        for (int j = 0; j < 4; ++j)
            #pragma unroll
            for (int l = 0; l < 4; ++l) c[i][j][l] = 0.0f;

    // loader mapping: each thread -> one row, 8 consecutive k (2x float4)
    const int tr_m = tid >> 1;          // 0..127
    const int tr_k = (tid & 1) << 3;    // 0 or 8

    const float* pA = A  + (size_t)(m0 + tr_m) * lda + tr_k;
    const float* pB = Bg + (size_t)(n0 + tr_m) * ldb + tr_k;

    // ldmatrix base addresses (byte, shared space)
    const uint32_t sAb = s2u(As);
    const uint32_t sBb = s2u(Bs);
    const int aRow = wm * 64 + ((lane >> 3) & 1) * 8 + (lane & 7);
    const int aK4  = (lane >> 4) * 4;                // 0 or 4 floats
    const uint32_t aAddr = sAb + (uint32_t)(aRow * PITCH + aK4) * 4u;
    const int l4 = lane & 15;
    const int bRow = wn * 32 + (l4 & 7);
    const int bK4  = ((l4 >> 3) & 1) * 4;
    const uint32_t bAddr = sBb + (uint32_t)(bRow * PITCH + bK4) * 4u;

    float4 ra0, ra1, rb0, rb1;
    ra0 = *(const float4*)pA; ra1 = *(const float4*)(pA + 4);
    rb0 = *(const float4*)pB; rb1 = *(const float4*)(pB + 4);

    const int ktiles = K / BK;
    for (int kt = 0; kt < ktiles; ++kt) {
        *(uint4*)&As[tr_m * PITCH + tr_k]     = tf4(ra0);
        *(uint4*)&As[tr_m * PITCH + tr_k + 4] = tf4(ra1);
        *(uint4*)&Bs[tr_m * PITCH + tr_k]     = tf4(rb0);
        *(uint4*)&Bs[tr_m * PITCH + tr_k + 4] = tf4(rb1);
        __syncthreads();

        if (kt + 1 < ktiles) {
            const float* nA = pA + (kt + 1) * BK;
            const float* nB = pB + (kt + 1) * BK;
            ra0 = *(const float4*)nA; ra1 = *(const float4*)(nA + 4);
            rb0 = *(const float4*)nB; rb1 = *(const float4*)(nB + 4);
        }

        #pragma unroll
        for (int kt2 = 0; kt2 < 2; ++kt2) {
            uint32_t af[4][4], bf[4][2];
            #pragma unroll
            for (int mi = 0; mi < 4; ++mi)
                ldsm4(af[mi], aAddr + (uint32_t)(mi * 16 * PITCH * 4 + kt2 * 32));
            #pragma unroll
            for (int ni = 0; ni < 4; ++ni)
                ldsm2(bf[ni], bAddr + (uint32_t)(ni * 8 * PITCH * 4 + kt2 * 32));
            #pragma unroll
            for (int mi = 0; mi < 4; ++mi)
                #pragma unroll
                for (int ni = 0; ni < 4; ++ni)
                    mma8(c[mi][ni], af[mi], bf[ni]);
        }
        __syncthreads();
    }

    // Epilogue
    #pragma unroll
    for (int mi = 0; mi < 4; ++mi) {
        const int row = m0 + wm * 64 + mi * 16 + gid;
        #pragma unroll
        for (int ni = 0; ni < 4; ++ni) {
            const int col = n0 + wn * 32 + ni * 8 + tig * 2;
            float* p0 = Cg + (size_t)row * ldc + col;
            float* p1 = p0 + (size_t)8 * ldc;
            float2 u0 = make_float2(alpha * c[mi][ni][0], alpha * c[mi][ni][1]);
            float2 u1 = make_float2(alpha * c[mi][ni][2], alpha * c[mi][ni][3]);
            if (ACC) {
                float2 e0 = *(float2*)p0, e1 = *(float2*)p1;
                u0.x += e0.x; u0.y += e0.y;
                u1.x += e1.x; u1.y += e1.y;
            }
            *(float2*)p0 = u0;
            *(float2*)p1 = u1;
        }
    }
}

// x[b][c][n] -> xT[b][n][c]
__global__ void __launch_bounds__(256) transpose_cn(
    const float* __restrict__ X, float* __restrict__ XT)
{
    __shared__ float t[32][33];
    const int b = blockIdx.z;
    const int c0 = blockIdx.y * 32;
    const int n0 = blockIdx.x * 32;
    const int tx = threadIdx.x, ty = threadIdx.y;
    #pragma unroll
    for (int i = 0; i < 4; ++i)
        t[ty + 8 * i][tx] = X[((size_t)b * CH + c0 + ty + 8 * i) * NSEQ + n0 + tx];
    __syncthreads();
    #pragma unroll
    for (int i = 0; i < 4; ++i)
        XT[((size_t)b * NSEQ + n0 + ty + 8 * i) * CH + c0 + tx] = t[tx][ty + 8 * i];
}

// Row softmax over contiguous last dim of g_sim, in place.
__global__ void __launch_bounds__(256) softmax_rows(float* __restrict__ S) {
    __shared__ float smax[8];
    __shared__ float ssum[8];
    const size_t rowoff = ((size_t)blockIdx.y * NSEQ + blockIdx.x) * NSEQ;
    float4* row = (float4*)(S + rowoff);
    const int t = threadIdx.x;

    float4 v[4];
    float mx = -3.0e38f;
    #pragma unroll
    for (int i = 0; i < 4; ++i) {
        v[i] = row[t + i * 256];
        mx = fmaxf(mx, fmaxf(fmaxf(v[i].x, v[i].y), fmaxf(v[i].z, v[i].w)));
    }
    #pragma unroll
    for (int o = 16; o > 0; o >>= 1) mx = fmaxf(mx, __shfl_xor_sync(0xffffffffu, mx, o));
    if ((t & 31) == 0) smax[t >> 5] = mx;
    __syncthreads();
    float bm = smax[0];
    #pragma unroll
    for (int w = 1; w < 8; ++w) bm = fmaxf(bm, smax[w]);

    float sum = 0.0f;
    #pragma unroll
    for (int i = 0; i < 4; ++i) {
        v[i].x = __expf(v[i].x - bm);
        v[i].y = __expf(v[i].y - bm);
        v[i].z = __expf(v[i].z - bm);
        v[i].w = __expf(v[i].w - bm);
        sum += v[i].x + v[i].y + v[i].z + v[i].w;
    }
    #pragma unroll
    for (int o = 16; o > 0; o >>= 1) sum += __shfl_xor_sync(0xffffffffu, sum, o);
    if ((t & 31) == 0) ssum[t >> 5] = sum;
    __syncthreads();
    float tot = 0.0f;
    #pragma unroll
    for (int w = 0; w < 8; ++w) tot += ssum[w];
    const float inv = 1.0f / tot;

    #pragma unroll
    for (int i = 0; i < 4; ++i) {
        v[i].x *= inv; v[i].y *= inv; v[i].z *= inv; v[i].w *= inv;
        row[t + i * 256] = v[i];
    }
}

extern "C" void kernel_launch(void* const* d_in, const int* in_sizes, int n_in,
                              void* d_out, int out_size) {
    const float* x  = (const float*)d_in[0];   // (B, C, N)
    const float* Wq = (const float*)d_in[1];   // (CT, C)
    const float* Wk = (const float*)d_in[2];   // (CT, C)
    const float* Wv = (const float*)d_in[3];   // (CT, C)
    const float* Wo = (const float*)d_in[4];   // (C, 2*CT)
    float* out = (float*)d_out;                // (B, C, N)
    (void)in_sizes; (void)n_in; (void)out_size;

    float *xt, *qp, *kp, *vp, *cp, *sp;
    cudaGetSymbolAddress((void**)&xt, g_xt);
    cudaGetSymbolAddress((void**)&qp, g_q);
    cudaGetSymbolAddress((void**)&kp, g_k);
    cudaGetSymbolAddress((void**)&vp, g_v);
    cudaGetSymbolAddress((void**)&cp, g_ctx);
    cudaGetSymbolAddress((void**)&sp, g_sim);

    const dim3 blk(256);
    const long long XS = (long long)CH * NSEQ;    // x / xT / out batch stride
    const long long PS = (long long)CTR * NSEQ;   // q/k/v/ctx batch stride
    const long long SS = (long long)NSEQ * NSEQ;  // sim batch stride

    // xT[b][n][c]
    transpose_cn<<<dim3(NSEQ / 32, CH / 32, BATCH), dim3(32, 8)>>>(x, xt);

    // q[b][n][ct] = sum_c xT[n][c] * Wq[ct][c]   (M=NSEQ, N=CTR)
    const dim3 gq(CTR / BN, NSEQ / BM, BATCH);
    gemm_rr<false><<<gq, blk>>>(xt, Wq, qp, CH, CH, CH, CTR, XS, 0, PS, 1.0f);
    gemm_rr<false><<<gq, blk>>>(xt, Wk, kp, CH, CH, CH, CTR, XS, 0, PS, 1.0f);

    // v[b][ct][n] = sum_c Wv[ct][c] * xT[n][c]   (M=CTR, N=NSEQ)
    const dim3 gv(NSEQ / BN, CTR / BM, BATCH);
    gemm_rr<false><<<gv, blk>>>(Wv, xt, vp, CH, CH, CH, NSEQ, 0, XS, PS, 1.0f);

    // sim[b][n][m] = (1/16) sum_ct q[n][ct] * k[m][ct]   (M=N=NSEQ)
    const dim3 gsim(NSEQ / BN, NSEQ / BM, BATCH);
    gemm_rr<false><<<gsim, blk>>>(qp, kp, sp, CTR, CTR, CTR, NSEQ, PS, PS, SS, 0.0625f);

    // softmax over m (contiguous), in place
    softmax_rows<<<dim3(NSEQ, BATCH), blk>>>(sp);

    // ctx[b][n][ct] = sum_m attn[n][m] * v[ct][m]   (M=NSEQ, N=CTR, K=NSEQ)
    const dim3 gctx(CTR / BN, NSEQ / BM, BATCH);
    gemm_rr<false><<<gctx, blk>>>(sp, vp, cp, NSEQ, NSEQ, NSEQ, CTR, SS, PS, PS, 1.0f);

    // out[b][o][n] = sum_ct Wo[o][ct]*ctx[n][ct] + sum_c Wo[o][CT+c]*xT[n][c]
    const dim3 gout(NSEQ / BN, CH / BM, BATCH);
    gemm_rr<false><<<gout, blk>>>(Wo,       cp, out, CTR, 2 * CTR, CTR, NSEQ, 0, PS, XS, 1.0f);
    gemm_rr<true ><<<gout, blk>>>(Wo + CTR, xt, out, CH,  2 * CTR, CH,  NSEQ, 0, XS, XS, 1.0f);
}

// round 3
// speedup vs baseline: 1.3957x; 1.2488x over previous
#include <cuda_runtime.h>
#include <cstdint>

#define BATCH 4
#define CH    256
#define NSEQ  4096
#define CTR   256

// Scratch (allocation-free rule: __device__ globals)
__device__ float g_w[3 * CTR * CH + CH * 2 * CTR];        // tf32-rounded Wq,Wk,Wv,Wo
__device__ float g_cat[BATCH * NSEQ * 2 * CTR];           // [b][n][0:256)=ctx, [256:512)=xT
__device__ float g_q[BATCH * NSEQ * CTR];                 // [b][n][ct]
__device__ float g_k[BATCH * NSEQ * CTR];                 // [b][n][ct]
__device__ float g_v[BATCH * CTR * NSEQ];                 // [b][ct][n]
__device__ float g_sim[(size_t)BATCH * NSEQ * NSEQ];      // [b][n][m]

#define BM 128
#define BN 128
#define BK 16
#define PITCH 20           // floats per smem row (16 used + 4 pad)
#define STAGES 4
#define ASZ (BM * PITCH)   // uint32 per operand per stage
#define STG (2 * ASZ)      // uint32 per stage (A + B)
#define SMEM_BYTES (STAGES * STG * 4)

__device__ __forceinline__ uint32_t f2tf(float x) {
    uint32_t r;
    asm("cvt.rna.tf32.f32 %0, %1;" : "=r"(r) : "f"(x));
    return r;
}
__device__ __forceinline__ float rtf(float x) { return __uint_as_float(f2tf(x)); }
__device__ __forceinline__ uint32_t s2u(const void* p) {
    return (uint32_t)__cvta_generic_to_shared(p);
}
__device__ __forceinline__ void mma8(float* c, const uint32_t* a, const uint32_t* b) {
    asm("mma.sync.aligned.m16n8k8.row.col.f32.tf32.tf32.f32 "
        "{%0,%1,%2,%3}, {%4,%5,%6,%7}, {%8,%9}, {%0,%1,%2,%3};"
        : "+f"(c[0]), "+f"(c[1]), "+f"(c[2]), "+f"(c[3])
        : "r"(a[0]), "r"(a[1]), "r"(a[2]), "r"(a[3]), "r"(b[0]), "r"(b[1]));
}
__device__ __forceinline__ void ldsm4(uint32_t* r, uint32_t addr) {
    asm volatile("ldmatrix.sync.aligned.m8n8.x4.shared.b16 {%0,%1,%2,%3}, [%4];"
                 : "=r"(r[0]), "=r"(r[1]), "=r"(r[2]), "=r"(r[3]) : "r"(addr));
}
__device__ __forceinline__ void ldsm2(uint32_t* r, uint32_t addr) {
    asm volatile("ldmatrix.sync.aligned.m8n8.x2.shared.b16 {%0,%1}, [%2];"
                 : "=r"(r[0]), "=r"(r[1]) : "r"(addr));
}
__device__ __forceinline__ void cpasync16(uint32_t d, const float* g) {
    asm volatile("cp.async.cg.shared.global [%0], [%1], 16;" :: "r"(d), "l"(g));
}
__device__ __forceinline__ void cpcommit() { asm volatile("cp.async.commit_group;"); }
__device__ __forceinline__ void cpwait() {
    asm volatile("cp.async.wait_group %0;" :: "n"(STAGES - 2));
}

// C[m,n] = alpha * sum_k A[m][k] * B[n][k]; operands already tf32-rounded fp32 bits.
// A: M x K rows (lda), B: N x K rows (ldb). Grid (N/BN, M/BM, batch), 256 threads.
template <bool ROUND>
__global__ void __launch_bounds__(256, 2) gemm_rr(
    const float* __restrict__ A, const float* __restrict__ Bg,
    float* __restrict__ Cg,
    int K, int lda, int ldb, int ldc,
    long long strideA, long long strideB, long long strideC,
    float alpha)
{
    extern __shared__ uint32_t sh[];

    const int tid = threadIdx.x;
    const int m0 = blockIdx.y * BM;
    const int n0 = blockIdx.x * BN;
    A  += (size_t)((long long)blockIdx.z * strideA);
    Bg += (size_t)((long long)blockIdx.z * strideB);
    Cg += (size_t)((long long)blockIdx.z * strideC);

    const int warp = tid >> 5;
    const int lane = tid & 31;
    const int wm = warp & 1;
    const int wn = warp >> 1;
    const int gid = lane >> 2;
    const int tig = lane & 3;

    float c[4][4][4];
    #pragma unroll
    for (int i = 0; i < 4; ++i)
        #pragma unroll
        for (int j = 0; j < 4; ++j)
            #pragma unroll
            for (int l = 0; l < 4; ++l) c[i][j][l] = 0.0f;

    // loader mapping: one row per thread-pair, 8 consecutive k each (2x 16B)
    const int tr_m = tid >> 1;
    const int tr_k = (tid & 1) << 3;
    const float* pA = A  + (size_t)(m0 + tr_m) * lda + tr_k;
    const float* pB = Bg + (size_t)(n0 + tr_m) * ldb + tr_k;

    const uint32_t sBase = s2u(sh);
    const uint32_t stA = sBase + (uint32_t)(tr_m * PITCH + tr_k) * 4u;
    const uint32_t stB = stA + (uint32_t)ASZ * 4u;

    // ldmatrix read addresses (proven mapping from round 2)
    const int aRow = wm * 64 + ((lane >> 3) & 1) * 8 + (lane & 7);
    const int aK4  = (lane >> 4) * 4;
    const uint32_t aAddr = sBase + (uint32_t)(aRow * PITCH + aK4) * 4u;
    const int l4 = lane & 15;
    const uint32_t bAddr = sBase +
        (uint32_t)(ASZ + (wn * 32 + (l4 & 7)) * PITCH + ((l4 >> 3) & 1) * 4) * 4u;

    const int ktiles = K / BK;

    auto issue = [&](int kt, int s) {
        const float* ga = pA + kt * BK;
        const float* gb = pB + kt * BK;
        const uint32_t off = (uint32_t)(s * STG * 4);
        cpasync16(stA + off,      ga);
        cpasync16(stA + off + 16, ga + 4);
        cpasync16(stB + off,      gb);
        cpasync16(stB + off + 16, gb + 4);
    };

    #pragma unroll
    for (int s = 0; s < STAGES - 1; ++s) { issue(s, s); cpcommit(); }

    for (int kt = 0; kt < ktiles; ++kt) {
        cpwait();                 // tile kt resident
        __syncthreads();          // all warps: tile ready, prev compute done
        if (kt + STAGES - 1 < ktiles) issue(kt + STAGES - 1, (kt + STAGES - 1) & (STAGES - 1));
        cpcommit();               // unconditional: keeps group accounting exact

        const uint32_t so = (uint32_t)((kt & (STAGES - 1)) * STG * 4);
        #pragma unroll
        for (int kt2 = 0; kt2 < 2; ++kt2) {
            uint32_t af[4][4], bf[4][2];
            #pragma unroll
            for (int mi = 0; mi < 4; ++mi)
                ldsm4(af[mi], aAddr + so + (uint32_t)(mi * 16 * PITCH * 4 + kt2 * 32));
            #pragma unroll
            for (int ni = 0; ni < 4; ++ni)
                ldsm2(bf[ni], bAddr + so + (uint32_t)(ni * 8 * PITCH * 4 + kt2 * 32));
            #pragma unroll
            for (int mi = 0; mi < 4; ++mi)
                #pragma unroll
                for (int ni = 0; ni < 4; ++ni)
                    mma8(c[mi][ni], af[mi], bf[ni]);
        }
    }

    // Epilogue
    #pragma unroll
    for (int mi = 0; mi < 4; ++mi) {
        const int row = m0 + wm * 64 + mi * 16 + gid;
        #pragma unroll
        for (int ni = 0; ni < 4; ++ni) {
            const int col = n0 + wn * 32 + ni * 8 + tig * 2;
            float* p0 = Cg + (size_t)row * ldc + col;
            float* p1 = p0 + (size_t)8 * ldc;
            float2 u0 = make_float2(alpha * c[mi][ni][0], alpha * c[mi][ni][1]);
            float2 u1 = make_float2(alpha * c[mi][ni][2], alpha * c[mi][ni][3]);
            if (ROUND) {
                u0.x = rtf(u0.x); u0.y = rtf(u0.y);
                u1.x = rtf(u1.x); u1.y = rtf(u1.y);
            }
            *(float2*)p0 = u0;
            *(float2*)p1 = u1;
        }
    }
}

// Round all weights to tf32 once.
__global__ void __launch_bounds__(256) prep_weights(
    const float* __restrict__ Wq, const float* __restrict__ Wk,
    const float* __restrict__ Wv, const float* __restrict__ Wo,
    float* __restrict__ dst)
{
    const int i = blockIdx.x * 256 + threadIdx.x;   // grid covers 327680
    float v;
    if (i < 65536)        v = Wq[i];
    else if (i < 131072)  v = Wk[i - 65536];
    else if (i < 196608)  v = Wv[i - 131072];
    else                  v = Wo[i - 196608];
    dst[i] = __uint_as_float(f2tf(v));
}

// x[b][c][n] -> cat[b][n][256 + c], tf32-rounded
__global__ void __launch_bounds__(256) transpose_cn(
    const float* __restrict__ X, float* __restrict__ CAT)
{
    __shared__ float t[32][33];
    const int b = blockIdx.z;
    const int c0 = blockIdx.y * 32;
    const int n0 = blockIdx.x * 32;
    const int tx = threadIdx.x, ty = threadIdx.y;
    #pragma unroll
    for (int i = 0; i < 4; ++i)
        t[ty + 8 * i][tx] = X[((size_t)b * CH + c0 + ty + 8 * i) * NSEQ + n0 + tx];
    __syncthreads();
    #pragma unroll
    for (int i = 0; i < 4; ++i)
        CAT[((size_t)b * NSEQ + n0 + ty + 8 * i) * (2 * CTR) + 256 + c0 + tx] =
            __uint_as_float(f2tf(t[tx][ty + 8 * i]));
}

// Row softmax over contiguous last dim of g_sim, in place; output tf32-rounded.
__global__ void __launch_bounds__(256) softmax_rows(float* __restrict__ S) {
    __shared__ float smax[8];
    __shared__ float ssum[8];
    const size_t rowoff = ((size_t)blockIdx.y * NSEQ + blockIdx.x) * NSEQ;
    float4* row = (float4*)(S + rowoff);
    const int t = threadIdx.x;

    float4 v[4];
    float mx = -3.0e38f;
    #pragma unroll
    for (int i = 0; i < 4; ++i) {
        v[i] = row[t + i * 256];
        mx = fmaxf(mx, fmaxf(fmaxf(v[i].x, v[i].y), fmaxf(v[i].z, v[i].w)));
    }
    #pragma unroll
    for (int o = 16; o > 0; o >>= 1) mx = fmaxf(mx, __shfl_xor_sync(0xffffffffu, mx, o));
    if ((t & 31) == 0) smax[t >> 5] = mx;
    __syncthreads();
    float bm = smax[0];
    #pragma unroll
    for (int w = 1; w < 8; ++w) bm = fmaxf(bm, smax[w]);

    float sum = 0.0f;
    #pragma unroll
    for (int i = 0; i < 4; ++i) {
        v[i].x = __expf(v[i].x - bm);
        v[i].y = __expf(v[i].y - bm);
        v[i].z = __expf(v[i].z - bm);
        v[i].w = __expf(v[i].w - bm);
        sum += v[i].x + v[i].y + v[i].z + v[i].w;
    }
    #pragma unroll
    for (int o = 16; o > 0; o >>= 1) sum += __shfl_xor_sync(0xffffffffu, sum, o);
    if ((t & 31) == 0) ssum[t >> 5] = sum;
    __syncthreads();
    float tot = 0.0f;
    #pragma unroll
    for (int w = 0; w < 8; ++w) tot += ssum[w];
    const float inv = 1.0f / tot;

    #pragma unroll
    for (int i = 0; i < 4; ++i) {
        v[i].x = __uint_as_float(f2tf(v[i].x * inv));
        v[i].y = __uint_as_float(f2tf(v[i].y * inv));
        v[i].z = __uint_as_float(f2tf(v[i].z * inv));
        v[i].w = __uint_as_float(f2tf(v[i].w * inv));
        row[t + i * 256] = v[i];
    }
}

extern "C" void kernel_launch(void* const* d_in, const int* in_sizes, int n_in,
                              void* d_out, int out_size) {
    const float* x  = (const float*)d_in[0];   // (B, C, N)
    const float* Wq = (const float*)d_in[1];   // (CT, C)
    const float* Wk = (const float*)d_in[2];   // (CT, C)
    const float* Wv = (const float*)d_in[3];   // (CT, C)
    const float* Wo = (const float*)d_in[4];   // (C, 2*CT)
    float* out = (float*)d_out;                // (B, C, N)
    (void)in_sizes; (void)n_in; (void)out_size;

    float *wp, *cat, *qp, *kp, *vp, *sp;
    cudaGetSymbolAddress((void**)&wp,  g_w);
    cudaGetSymbolAddress((void**)&cat, g_cat);
    cudaGetSymbolAddress((void**)&qp,  g_q);
    cudaGetSymbolAddress((void**)&kp,  g_k);
    cudaGetSymbolAddress((void**)&vp,  g_v);
    cudaGetSymbolAddress((void**)&sp,  g_sim);

    cudaFuncSetAttribute(gemm_rr<false>, cudaFuncAttributeMaxDynamicSharedMemorySize, SMEM_BYTES);
    cudaFuncSetAttribute(gemm_rr<true>,  cudaFuncAttributeMaxDynamicSharedMemorySize, SMEM_BYTES);

    const dim3 blk(256);
    const long long CS = (long long)NSEQ * 2 * CTR;   // cat batch stride
    const long long PS = (long long)NSEQ * CTR;       // q/k/v batch stride
    const long long SS = (long long)NSEQ * NSEQ;      // sim batch stride
    const long long XS = (long long)CH * NSEQ;        // out batch stride

    prep_weights<<<1280, blk>>>(Wq, Wk, Wv, Wo, wp);
    transpose_cn<<<dim3(NSEQ / 32, CH / 32, BATCH), dim3(32, 8)>>>(x, cat);

    // q[b][n][ct] = sum_c xT[n][c] * Wq[ct][c]
    const dim3 gq(CTR / BN, NSEQ / BM, BATCH);
    gemm_rr<true><<<gq, blk, SMEM_BYTES>>>(cat + 256, wp,         qp, CH, 2 * CTR, CH, CTR, CS, 0, PS, 1.0f);
    gemm_rr<true><<<gq, blk, SMEM_BYTES>>>(cat + 256, wp + 65536, kp, CH, 2 * CTR, CH, CTR, CS, 0, PS, 1.0f);

    // v[b][ct][n] = sum_c Wv[ct][c] * xT[n][c]
    const dim3 gv(NSEQ / BN, CTR / BM, BATCH);
    gemm_rr<true><<<gv, blk, SMEM_BYTES>>>(wp + 131072, cat + 256, vp, CH, CH, 2 * CTR, NSEQ, 0, CS, PS, 1.0f);

    // sim[b][n][m] = (1/16) sum_ct q[n][ct] * k[m][ct]
    const dim3 gsim(NSEQ / BN, NSEQ / BM, BATCH);
    gemm_rr<false><<<gsim, blk, SMEM_BYTES>>>(qp, kp, sp, CTR, CTR, CTR, NSEQ, PS, PS, SS, 0.0625f);

    softmax_rows<<<dim3(NSEQ, BATCH), blk>>>(sp);

    // ctx -> cat[b][n][0:256): sum_m attn[n][m] * v[ct][m]
    const dim3 gctx(CTR / BN, NSEQ / BM, BATCH);
    gemm_rr<true><<<gctx, blk, SMEM_BYTES>>>(sp, vp, cat, NSEQ, NSEQ, NSEQ, 2 * CTR, SS, PS, CS, 1.0f);

    // out[b][o][n] = sum_{k<512} Wo[o][k] * cat[n][k]
    const dim3 gout(NSEQ / BN, CH / BM, BATCH);
    gemm_rr<false><<<gout, blk, SMEM_BYTES>>>(wp + 196608, cat, out, 2 * CTR, 2 * CTR, 2 * CTR, NSEQ, 0, CS, XS, 1.0f);
}

// round 6
// speedup vs baseline: 2.6102x; 1.8702x over previous
#include <cuda_runtime.h>
#include <cuda_fp16.h>
#include <cstdint>

#define BATCH 4
#define CH    256
#define NSEQ  4096
#define CTR   256

// Scratch (allocation-free rule: __device__ globals)
__device__ __half g_wh[3 * CTR * CH + CH * 2 * CTR];        // half Wq,Wk,Wv,Wo
__device__ __half g_cat[BATCH * NSEQ * 2 * CTR];            // [b][n][0:256)=ctx, [256:512)=xT
__device__ __half g_q[BATCH * NSEQ * CTR];                  // [b][n][ct]
__device__ __half g_k[BATCH * NSEQ * CTR];                  // [b][n][ct]
__device__ __half g_v[BATCH * CTR * NSEQ];                  // [b][ct][n]
__device__ float  g_sim[(size_t)BATCH * NSEQ * NSEQ];       // [b][n][m] logits, f32
__device__ __half g_attn[(size_t)BATCH * NSEQ * NSEQ];      // [b][n][m] weights, half

#define BM 128
#define BN 128
#define BK 32              // halves per k-tile
#define PITCH_H 40         // halves per smem row (32 used + 8 pad) -> conflict-free LDSM
#define STAGES 4
#define A_STG_H (BM * PITCH_H)             // 5120 halves
#define STG_B   (2 * A_STG_H * 2)          // bytes per stage (A+B) = 20480
#define SMEM_BYTES (STAGES * STG_B)        // 81920

__device__ __forceinline__ uint32_t s2u(const void* p) {
    return (uint32_t)__cvta_generic_to_shared(p);
}
__device__ __forceinline__ void mma16(float* c, const uint32_t* a, const uint32_t* b) {
    asm("mma.sync.aligned.m16n8k16.row.col.f32.f16.f16.f32 "
        "{%0,%1,%2,%3}, {%4,%5,%6,%7}, {%8,%9}, {%0,%1,%2,%3};"
        : "+f"(c[0]), "+f"(c[1]), "+f"(c[2]), "+f"(c[3])
        : "r"(a[0]), "r"(a[1]), "r"(a[2]), "r"(a[3]), "r"(b[0]), "r"(b[1]));
}
__device__ __forceinline__ void ldsm4(uint32_t* r, uint32_t addr) {
    asm volatile("ldmatrix.sync.aligned.m8n8.x4.shared.b16 {%0,%1,%2,%3}, [%4];"
                 : "=r"(r[0]), "=r"(r[1]), "=r"(r[2]), "=r"(r[3]) : "r"(addr));
}
__device__ __forceinline__ void ldsm2(uint32_t* r, uint32_t addr) {
    asm volatile("ldmatrix.sync.aligned.m8n8.x2.shared.b16 {%0,%1}, [%2];"
                 : "=r"(r[0]), "=r"(r[1]) : "r"(addr));
}
__device__ __forceinline__ void cpasync16(uint32_t d, const void* g) {
    asm volatile("cp.async.cg.shared.global [%0], [%1], 16;" :: "r"(d), "l"(g));
}
__device__ __forceinline__ void cpcommit() { asm volatile("cp.async.commit_group;"); }
__device__ __forceinline__ void cpwait() {
    asm volatile("cp.async.wait_group %0;" :: "n"(STAGES - 2));
}

// C[m,n] = alpha * sum_k A[m][k] * B[n][k].  A: MxK half rows (lda), B: NxK half
// rows (ldb). OutT float or __half. Grid (N/BN, M/BM, batch), 256 threads.
template <typename OutT>
__global__ void __launch_bounds__(256, 2) gemm_h(
    const __half* __restrict__ A, const __half* __restrict__ Bg,
    OutT* __restrict__ Cg,
    int K, int lda, int ldb, int ldc,
    long long strideA, long long strideB, long long strideC,
    float alpha)
{
    extern __shared__ __half sh[];

    const int tid = threadIdx.x;
    const int m0 = blockIdx.y * BM;
    const int n0 = blockIdx.x * BN;
    A  += (size_t)((long long)blockIdx.z * strideA);
    Bg += (size_t)((long long)blockIdx.z * strideB);
    Cg += (size_t)((long long)blockIdx.z * strideC);

    const int warp = tid >> 5;
    const int lane = tid & 31;
    const int wm = warp & 1;      // 2 warps along M: 64 rows each
    const int wn = warp >> 1;     // 4 warps along N: 32 cols each
    const int gid = lane >> 2;
    const int tig = lane & 3;

    float c[4][4][4];
    #pragma unroll
    for (int i = 0; i < 4; ++i)
        #pragma unroll
        for (int j = 0; j < 4; ++j)
            #pragma unroll
            for (int l = 0; l < 4; ++l) c[i][j][l] = 0.0f;

    // Loader: 512 16B-chunks per operand tile (128 rows x 4), 2 per thread.
    const int row0 = tid >> 2;            // 0..63
    const int k0   = (tid & 3) * 8;       // halves
    const __half* pA0 = A  + (size_t)(m0 + row0) * lda + k0;
    const __half* pA1 = pA0 + (size_t)64 * lda;
    const __half* pB0 = Bg + (size_t)(n0 + row0) * ldb + k0;
    const __half* pB1 = pB0 + (size_t)64 * ldb;

    const uint32_t sBase = s2u(sh);
    const uint32_t oA0 = (uint32_t)(row0 * PITCH_H + k0) * 2u;
    const uint32_t oA1 = oA0 + 64u * PITCH_H * 2u;
    const uint32_t oB0 = oA0 + (uint32_t)A_STG_H * 2u;
    const uint32_t oB1 = oA1 + (uint32_t)A_STG_H * 2u;

    // ldmatrix read addresses
    const uint32_t aAddr = sBase +
        (uint32_t)((wm * 64 + (lane & 15)) * PITCH_H + (lane >> 4) * 8) * 2u;
    const int l4 = lane & 15;
    const uint32_t bAddr = sBase + (uint32_t)A_STG_H * 2u +
        (uint32_t)((wn * 32 + (l4 & 7)) * PITCH_H + ((l4 >> 3) & 1) * 8) * 2u;

    const int ktiles = K / BK;

    auto issue = [&](int kt, int s) {
        const uint32_t so = (uint32_t)(s * STG_B);
        const int g = kt * BK;
        cpasync16(sBase + so + oA0, pA0 + g);
        cpasync16(sBase + so + oA1, pA1 + g);
        cpasync16(sBase + so + oB0, pB0 + g);
        cpasync16(sBase + so + oB1, pB1 + g);
    };

    #pragma unroll
    for (int s = 0; s < STAGES - 1; ++s) { issue(s, s); cpcommit(); }

    for (int kt = 0; kt < ktiles; ++kt) {
        cpwait();
        __syncthreads();
        if (kt + STAGES - 1 < ktiles) issue(kt + STAGES - 1, (kt + STAGES - 1) & (STAGES - 1));
        cpcommit();

        const uint32_t so = (uint32_t)((kt & (STAGES - 1)) * STG_B);
        #pragma unroll
        for (int kt2 = 0; kt2 < 2; ++kt2) {        // two k16 steps per tile
            uint32_t af[4][4], bf[4][2];
            #pragma unroll
            for (int mi = 0; mi < 4; ++mi)
                ldsm4(af[mi], aAddr + so + (uint32_t)(mi * 16 * PITCH_H * 2 + kt2 * 32));
            #pragma unroll
            for (int ni = 0; ni < 4; ++ni)
                ldsm2(bf[ni], bAddr + so + (uint32_t)(ni * 8 * PITCH_H * 2 + kt2 * 32));
            #pragma unroll
            for (int mi = 0; mi < 4; ++mi)
                #pragma unroll
                for (int ni = 0; ni < 4; ++ni)
                    mma16(c[mi][ni], af[mi], bf[ni]);
        }
    }

    // Epilogue (m16n8 accumulator layout)
    #pragma unroll
    for (int mi = 0; mi < 4; ++mi) {
        const int row = m0 + wm * 64 + mi * 16 + gid;
        #pragma unroll
        for (int ni = 0; ni < 4; ++ni) {
            const int col = n0 + wn * 32 + ni * 8 + tig * 2;
            const float v00 = alpha * c[mi][ni][0], v01 = alpha * c[mi][ni][1];
            const float v10 = alpha * c[mi][ni][2], v11 = alpha * c[mi][ni][3];
            if (sizeof(OutT) == 2) {
                __half2* p0 = (__half2*)((__half*)Cg + (size_t)row * ldc + col);
                __half2* p1 = (__half2*)((__half*)Cg + (size_t)(row + 8) * ldc + col);
                *p0 = __floats2half2_rn(v00, v01);
                *p1 = __floats2half2_rn(v10, v11);
            } else {
                float* p0 = (float*)Cg + (size_t)row * ldc + col;
                float* p1 = p0 + (size_t)8 * ldc;
                *(float2*)p0 = make_float2(v00, v01);
                *(float2*)p1 = make_float2(v10, v11);
            }
        }
    }
}

// Round all weights to half once.
__global__ void __launch_bounds__(256) prep_weights(
    const float* __restrict__ Wq, const float* __restrict__ Wk,
    const float* __restrict__ Wv, const float* __restrict__ Wo,
    __half* __restrict__ dst)
{
    const int i = blockIdx.x * 256 + threadIdx.x;   // grid covers 327680
    float v;
    if (i < 65536)        v = Wq[i];
    else if (i < 131072)  v = Wk[i - 65536];
    else if (i < 196608)  v = Wv[i - 131072];
    else                  v = Wo[i - 196608];
    dst[i] = __float2half_rn(v);
}

// x[b][c][n] -> cat[b][n][256 + c] as half
__global__ void __launch_bounds__(256) transpose_cn(
    const float* __restrict__ X, __half* __restrict__ CAT)
{
    __shared__ float t[32][33];
    const int b = blockIdx.z;
    const int c0 = blockIdx.y * 32;
    const int n0 = blockIdx.x * 32;
    const int tx = threadIdx.x, ty = threadIdx.y;
    #pragma unroll
    for (int i = 0; i < 4; ++i)
        t[ty + 8 * i][tx] = X[((size_t)b * CH + c0 + ty + 8 * i) * NSEQ + n0 + tx];
    __syncthreads();
    #pragma unroll
    for (int i = 0; i < 4; ++i)
        CAT[((size_t)b * NSEQ + n0 + ty + 8 * i) * (2 * CTR) + 256 + c0 + tx] =
            __float2half_rn(t[tx][ty + 8 * i]);
}

// Row softmax: read f32 logits, write half weights.
__global__ void __launch_bounds__(256) softmax_rows(
    const float* __restrict__ S, __half* __restrict__ P)
{
    __shared__ float smax[8];
    __shared__ float ssum[8];
    const size_t rowoff = ((size_t)blockIdx.y * NSEQ + blockIdx.x) * NSEQ;
    const float4* row = (const float4*)(S + rowoff);
    __half2* prow = (__half2*)(P + rowoff);
    const int t = threadIdx.x;

    float4 v[4];
    float mx = -3.0e38f;
    #pragma unroll
    for (int i = 0; i < 4; ++i) {
        v[i] = row[t + i * 256];
        mx = fmaxf(mx, fmaxf(fmaxf(v[i].x, v[i].y), fmaxf(v[i].z, v[i].w)));
    }
    #pragma unroll
    for (int o = 16; o > 0; o >>= 1) mx = fmaxf(mx, __shfl_xor_sync(0xffffffffu, mx, o));
    if ((t & 31) == 0) smax[t >> 5] = mx;
    __syncthreads();
    float bm = smax[0];
    #pragma unroll
    for (int w = 1; w < 8; ++w) bm = fmaxf(bm, smax[w]);

    float sum = 0.0f;
    #pragma unroll
    for (int i = 0; i < 4; ++i) {
        v[i].x = __expf(v[i].x - bm);
        v[i].y = __expf(v[i].y - bm);
        v[i].z = __expf(v[i].z - bm);
        v[i].w = __expf(v[i].w - bm);
        sum += v[i].x + v[i].y + v[i].z + v[i].w;
    }
    #pragma unroll
    for (int o = 16; o > 0; o >>= 1) sum += __shfl_xor_sync(0xffffffffu, sum, o);
    if ((t & 31) == 0) ssum[t >> 5] = sum;
    __syncthreads();
    float tot = 0.0f;
    #pragma unroll
    for (int w = 0; w < 8; ++w) tot += ssum[w];
    const float inv = 1.0f / tot;

    #pragma unroll
    for (int i = 0; i < 4; ++i) {
        const int j = t + i * 256;
        prow[2 * j]     = __floats2half2_rn(v[i].x * inv, v[i].y * inv);
        prow[2 * j + 1] = __floats2half2_rn(v[i].z * inv, v[i].w * inv);
    }
}

extern "C" void kernel_launch(void* const* d_in, const int* in_sizes, int n_in,
                              void* d_out, int out_size) {
    const float* x  = (const float*)d_in[0];   // (B, C, N)
    const float* Wq = (const float*)d_in[1];   // (CT, C)
    const float* Wk = (const float*)d_in[2];   // (CT, C)
    const float* Wv = (const float*)d_in[3];   // (CT, C)
    const float* Wo = (const float*)d_in[4];   // (C, 2*CT)
    float* out = (float*)d_out;                // (B, C, N)
    (void)in_sizes; (void)n_in; (void)out_size;

    __half *wh, *cat, *qp, *kp, *vp, *ap;
    float *sp;
    cudaGetSymbolAddress((void**)&wh,  g_wh);
    cudaGetSymbolAddress((void**)&cat, g_cat);
    cudaGetSymbolAddress((void**)&qp,  g_q);
    cudaGetSymbolAddress((void**)&kp,  g_k);
    cudaGetSymbolAddress((void**)&vp,  g_v);
    cudaGetSymbolAddress((void**)&sp,  g_sim);
    cudaGetSymbolAddress((void**)&ap,  g_attn);

    cudaFuncSetAttribute(gemm_h<float>,  cudaFuncAttributeMaxDynamicSharedMemorySize, SMEM_BYTES);
    cudaFuncSetAttribute(gemm_h<__half>, cudaFuncAttributeMaxDynamicSharedMemorySize, SMEM_BYTES);

    const dim3 blk(256);
    const long long CS = (long long)NSEQ * 2 * CTR;   // cat batch stride
    const long long PS = (long long)NSEQ * CTR;       // q/k/v batch stride
    const long long SS = (long long)NSEQ * NSEQ;      // sim/attn batch stride
    const long long XS = (long long)CH * NSEQ;        // out batch stride

    prep_weights<<<1280, blk>>>(Wq, Wk, Wv, Wo, wh);
    transpose_cn<<<dim3(NSEQ / 32, CH / 32, BATCH), dim3(32, 8)>>>(x, cat);

    // q[b][n][ct] = sum_c xT[n][c] * Wq[ct][c]
    const dim3 gq(CTR / BN, NSEQ / BM, BATCH);
    gemm_h<__half><<<gq, blk, SMEM_BYTES>>>(cat + 256, wh,         qp, CH, 2 * CTR, CH, CTR, CS, 0, PS, 1.0f);
    gemm_h<__half><<<gq, blk, SMEM_BYTES>>>(cat + 256, wh + 65536, kp, CH, 2 * CTR, CH, CTR, CS, 0, PS, 1.0f);

    // v[b][ct][n] = sum_c Wv[ct][c] * xT[n][c]
    const dim3 gv(NSEQ / BN, CTR / BM, BATCH);
    gemm_h<__half><<<gv, blk, SMEM_BYTES>>>(wh + 131072, cat + 256, vp, CH, CH, 2 * CTR, NSEQ, 0, CS, PS, 1.0f);

    // sim[b][n][m] = (1/16) sum_ct q[n][ct] * k[m][ct]  (f32 logits)
    const dim3 gsim(NSEQ / BN, NSEQ / BM, BATCH);
    gemm_h<float><<<gsim, blk, SMEM_BYTES>>>(qp, kp, sp, CTR, CTR, CTR, NSEQ, PS, PS, SS, 0.0625f);

    softmax_rows<<<dim3(NSEQ, BATCH), blk>>>(sp, ap);

    // ctx -> cat[b][n][0:256): sum_m attn[n][m] * v[ct][m]
    const dim3 gctx(CTR / BN, NSEQ / BM, BATCH);
    gemm_h<__half><<<gctx, blk, SMEM_BYTES>>>(ap, vp, cat, NSEQ, NSEQ, NSEQ, 2 * CTR, SS, PS, CS, 1.0f);

    // out[b][o][n] = sum_{k<512} Wo[o][k] * cat[n][k]
    const dim3 gout(NSEQ / BN, CH / BM, BATCH);
    gemm_h<float><<<gout, blk, SMEM_BYTES>>>(wh + 196608, cat, out, 2 * CTR, 2 * CTR, 2 * CTR, NSEQ, 0, CS, XS, 1.0f);
}

// round 7
// speedup vs baseline: 2.6104x; 1.0001x over previous
#include <cuda_runtime.h>
#include <cuda_fp16.h>
#include <cstdint>

#define BATCH 4
#define CH    256
#define NSEQ  4096
#define CTR   256

// Scratch (allocation-free rule: __device__ globals)
__device__ __half g_wh[3 * CTR * CH + CH * 2 * CTR];        // half Wq,Wk,Wv,Wo
__device__ __half g_cat[BATCH * NSEQ * 2 * CTR];            // [b][n][0:256)=ctx, [256:512)=xT
__device__ __half g_q[BATCH * NSEQ * CTR];                  // [b][n][ct]
__device__ __half g_k[BATCH * NSEQ * CTR];                  // [b][n][ct]
__device__ __half g_v[BATCH * CTR * NSEQ];                  // [b][ct][n]
__device__ float  g_sim[(size_t)BATCH * NSEQ * NSEQ];       // [b][n][m] logits, f32
__device__ __half g_attn[(size_t)BATCH * NSEQ * NSEQ];      // [b][n][m] weights, half

#define BM 128
#define BN 128
#define BK 32              // halves per k-tile
#define PITCH_H 40         // halves per smem row (32 used + 8 pad) -> conflict-free LDSM
#define STAGES 4
#define A_STG_H (BM * PITCH_H)             // 5120 halves
#define STG_B   (2 * A_STG_H * 2)          // bytes per stage (A+B) = 20480
#define SMEM_BYTES (STAGES * STG_B)        // 81920

__device__ __forceinline__ uint32_t s2u(const void* p) {
    return (uint32_t)__cvta_generic_to_shared(p);
}
__device__ __forceinline__ void mma16(float* c, const uint32_t* a, const uint32_t* b) {
    asm("mma.sync.aligned.m16n8k16.row.col.f32.f16.f16.f32 "
        "{%0,%1,%2,%3}, {%4,%5,%6,%7}, {%8,%9}, {%0,%1,%2,%3};"
        : "+f"(c[0]), "+f"(c[1]), "+f"(c[2]), "+f"(c[3])
        : "r"(a[0]), "r"(a[1]), "r"(a[2]), "r"(a[3]), "r"(b[0]), "r"(b[1]));
}
__device__ __forceinline__ void ldsm4(uint32_t* r, uint32_t addr) {
    asm volatile("ldmatrix.sync.aligned.m8n8.x4.shared.b16 {%0,%1,%2,%3}, [%4];"
                 : "=r"(r[0]), "=r"(r[1]), "=r"(r[2]), "=r"(r[3]) : "r"(addr));
}
__device__ __forceinline__ void ldsm2(uint32_t* r, uint32_t addr) {
    asm volatile("ldmatrix.sync.aligned.m8n8.x2.shared.b16 {%0,%1}, [%2];"
                 : "=r"(r[0]), "=r"(r[1]) : "r"(addr));
}
__device__ __forceinline__ void cpasync16(uint32_t d, const void* g) {
    asm volatile("cp.async.cg.shared.global [%0], [%1], 16;" :: "r"(d), "l"(g));
}
__device__ __forceinline__ void cpcommit() { asm volatile("cp.async.commit_group;"); }
__device__ __forceinline__ void cpwait() {
    asm volatile("cp.async.wait_group %0;" :: "n"(STAGES - 2));
}

// C[m,n] = alpha * sum_k A[m][k] * B[n][k].  A: MxK half rows (lda), B: NxK half
// rows (ldb). OutT float or __half. Grid (N/BN, M/BM, batch), 256 threads.
template <typename OutT>
__global__ void __launch_bounds__(256, 2) gemm_h(
    const __half* __restrict__ A, const __half* __restrict__ Bg,
    OutT* __restrict__ Cg,
    int K, int lda, int ldb, int ldc,
    long long strideA, long long strideB, long long strideC,
    float alpha)
{
    extern __shared__ __half sh[];

    const int tid = threadIdx.x;
    const int m0 = blockIdx.y * BM;
    const int n0 = blockIdx.x * BN;
    A  += (size_t)((long long)blockIdx.z * strideA);
    Bg += (size_t)((long long)blockIdx.z * strideB);
    Cg += (size_t)((long long)blockIdx.z * strideC);

    const int warp = tid >> 5;
    const int lane = tid & 31;
    const int wm = warp & 1;      // 2 warps along M: 64 rows each
    const int wn = warp >> 1;     // 4 warps along N: 32 cols each
    const int gid = lane >> 2;
    const int tig = lane & 3;

    float c[4][4][4];
    #pragma unroll
    for (int i = 0; i < 4; ++i)
        #pragma unroll
        for (int j = 0; j < 4; ++j)
            #pragma unroll
            for (int l = 0; l < 4; ++l) c[i][j][l] = 0.0f;

    // Loader: 512 16B-chunks per operand tile (128 rows x 4), 2 per thread.
    const int row0 = tid >> 2;            // 0..63
    const int k0   = (tid & 3) * 8;       // halves
    const __half* pA0 = A  + (size_t)(m0 + row0) * lda + k0;
    const __half* pA1 = pA0 + (size_t)64 * lda;
    const __half* pB0 = Bg + (size_t)(n0 + row0) * ldb + k0;
    const __half* pB1 = pB0 + (size_t)64 * ldb;

    const uint32_t sBase = s2u(sh);
    const uint32_t oA0 = (uint32_t)(row0 * PITCH_H + k0) * 2u;
    const uint32_t oA1 = oA0 + 64u * PITCH_H * 2u;
    const uint32_t oB0 = oA0 + (uint32_t)A_STG_H * 2u;
    const uint32_t oB1 = oA1 + (uint32_t)A_STG_H * 2u;

    // ldmatrix read addresses
    const uint32_t aAddr = sBase +
        (uint32_t)((wm * 64 + (lane & 15)) * PITCH_H + (lane >> 4) * 8) * 2u;
    const int l4 = lane & 15;
    const uint32_t bAddr = sBase + (uint32_t)A_STG_H * 2u +
        (uint32_t)((wn * 32 + (l4 & 7)) * PITCH_H + ((l4 >> 3) & 1) * 8) * 2u;

    const int ktiles = K / BK;

    auto issue = [&](int kt, int s) {
        const uint32_t so = (uint32_t)(s * STG_B);
        const int g = kt * BK;
        cpasync16(sBase + so + oA0, pA0 + g);
        cpasync16(sBase + so + oA1, pA1 + g);
        cpasync16(sBase + so + oB0, pB0 + g);
        cpasync16(sBase + so + oB1, pB1 + g);
    };

    #pragma unroll
    for (int s = 0; s < STAGES - 1; ++s) { issue(s, s); cpcommit(); }

    for (int kt = 0; kt < ktiles; ++kt) {
        cpwait();
        __syncthreads();
        if (kt + STAGES - 1 < ktiles) issue(kt + STAGES - 1, (kt + STAGES - 1) & (STAGES - 1));
        cpcommit();

        const uint32_t so = (uint32_t)((kt & (STAGES - 1)) * STG_B);
        #pragma unroll
        for (int kt2 = 0; kt2 < 2; ++kt2) {        // two k16 steps per tile
            uint32_t af[4][4], bf[4][2];
            #pragma unroll
            for (int mi = 0; mi < 4; ++mi)
                ldsm4(af[mi], aAddr + so + (uint32_t)(mi * 16 * PITCH_H * 2 + kt2 * 32));
            #pragma unroll
            for (int ni = 0; ni < 4; ++ni)
                ldsm2(bf[ni], bAddr + so + (uint32_t)(ni * 8 * PITCH_H * 2 + kt2 * 32));
            #pragma unroll
            for (int mi = 0; mi < 4; ++mi)
                #pragma unroll
                for (int ni = 0; ni < 4; ++ni)
                    mma16(c[mi][ni], af[mi], bf[ni]);
        }
    }

    // Epilogue (m16n8 accumulator layout)
    #pragma unroll
    for (int mi = 0; mi < 4; ++mi) {
        const int row = m0 + wm * 64 + mi * 16 + gid;
        #pragma unroll
        for (int ni = 0; ni < 4; ++ni) {
            const int col = n0 + wn * 32 + ni * 8 + tig * 2;
            const float v00 = alpha * c[mi][ni][0], v01 = alpha * c[mi][ni][1];
            const float v10 = alpha * c[mi][ni][2], v11 = alpha * c[mi][ni][3];
            if (sizeof(OutT) == 2) {
                __half2* p0 = (__half2*)((__half*)Cg + (size_t)row * ldc + col);
                __half2* p1 = (__half2*)((__half*)Cg + (size_t)(row + 8) * ldc + col);
                *p0 = __floats2half2_rn(v00, v01);
                *p1 = __floats2half2_rn(v10, v11);
            } else {
                float* p0 = (float*)Cg + (size_t)row * ldc + col;
                float* p1 = p0 + (size_t)8 * ldc;
                *(float2*)p0 = make_float2(v00, v01);
                *(float2*)p1 = make_float2(v10, v11);
            }
        }
    }
}

// Round all weights to half once.
__global__ void __launch_bounds__(256) prep_weights(
    const float* __restrict__ Wq, const float* __restrict__ Wk,
    const float* __restrict__ Wv, const float* __restrict__ Wo,
    __half* __restrict__ dst)
{
    const int i = blockIdx.x * 256 + threadIdx.x;   // grid covers 327680
    float v;
    if (i < 65536)        v = Wq[i];
    else if (i < 131072)  v = Wk[i - 65536];
    else if (i < 196608)  v = Wv[i - 131072];
    else                  v = Wo[i - 196608];
    dst[i] = __float2half_rn(v);
}

// x[b][c][n] -> cat[b][n][256 + c] as half
__global__ void __launch_bounds__(256) transpose_cn(
    const float* __restrict__ X, __half* __restrict__ CAT)
{
    __shared__ float t[32][33];
    const int b = blockIdx.z;
    const int c0 = blockIdx.y * 32;
    const int n0 = blockIdx.x * 32;
    const int tx = threadIdx.x, ty = threadIdx.y;
    #pragma unroll
    for (int i = 0; i < 4; ++i)
        t[ty + 8 * i][tx] = X[((size_t)b * CH + c0 + ty + 8 * i) * NSEQ + n0 + tx];
    __syncthreads();
    #pragma unroll
    for (int i = 0; i < 4; ++i)
        CAT[((size_t)b * NSEQ + n0 + ty + 8 * i) * (2 * CTR) + 256 + c0 + tx] =
            __float2half_rn(t[tx][ty + 8 * i]);
}

// Row softmax: read f32 logits, write half weights.
__global__ void __launch_bounds__(256) softmax_rows(
    const float* __restrict__ S, __half* __restrict__ P)
{
    __shared__ float smax[8];
    __shared__ float ssum[8];
    const size_t rowoff = ((size_t)blockIdx.y * NSEQ + blockIdx.x) * NSEQ;
    const float4* row = (const float4*)(S + rowoff);
    __half2* prow = (__half2*)(P + rowoff);
    const int t = threadIdx.x;

    float4 v[4];
    float mx = -3.0e38f;
    #pragma unroll
    for (int i = 0; i < 4; ++i) {
        v[i] = row[t + i * 256];
        mx = fmaxf(mx, fmaxf(fmaxf(v[i].x, v[i].y), fmaxf(v[i].z, v[i].w)));
    }
    #pragma unroll
    for (int o = 16; o > 0; o >>= 1) mx = fmaxf(mx, __shfl_xor_sync(0xffffffffu, mx, o));
    if ((t & 31) == 0) smax[t >> 5] = mx;
    __syncthreads();
    float bm = smax[0];
    #pragma unroll
    for (int w = 1; w < 8; ++w) bm = fmaxf(bm, smax[w]);

    float sum = 0.0f;
    #pragma unroll
    for (int i = 0; i < 4; ++i) {
        v[i].x = __expf(v[i].x - bm);
        v[i].y = __expf(v[i].y - bm);
        v[i].z = __expf(v[i].z - bm);
        v[i].w = __expf(v[i].w - bm);
        sum += v[i].x + v[i].y + v[i].z + v[i].w;
    }
    #pragma unroll
    for (int o = 16; o > 0; o >>= 1) sum += __shfl_xor_sync(0xffffffffu, sum, o);
    if ((t & 31) == 0) ssum[t >> 5] = sum;
    __syncthreads();
    float tot = 0.0f;
    #pragma unroll
    for (int w = 0; w < 8; ++w) tot += ssum[w];
    const float inv = 1.0f / tot;

    #pragma unroll
    for (int i = 0; i < 4; ++i) {
        const int j = t + i * 256;
        prow[2 * j]     = __floats2half2_rn(v[i].x * inv, v[i].y * inv);
        prow[2 * j + 1] = __floats2half2_rn(v[i].z * inv, v[i].w * inv);
    }
}

extern "C" void kernel_launch(void* const* d_in, const int* in_sizes, int n_in,
                              void* d_out, int out_size) {
    const float* x  = (const float*)d_in[0];   // (B, C, N)
    const float* Wq = (const float*)d_in[1];   // (CT, C)
    const float* Wk = (const float*)d_in[2];   // (CT, C)
    const float* Wv = (const float*)d_in[3];   // (CT, C)
    const float* Wo = (const float*)d_in[4];   // (C, 2*CT)
    float* out = (float*)d_out;                // (B, C, N)
    (void)in_sizes; (void)n_in; (void)out_size;

    __half *wh, *cat, *qp, *kp, *vp, *ap;
    float *sp;
    cudaGetSymbolAddress((void**)&wh,  g_wh);
    cudaGetSymbolAddress((void**)&cat, g_cat);
    cudaGetSymbolAddress((void**)&qp,  g_q);
    cudaGetSymbolAddress((void**)&kp,  g_k);
    cudaGetSymbolAddress((void**)&vp,  g_v);
    cudaGetSymbolAddress((void**)&sp,  g_sim);
    cudaGetSymbolAddress((void**)&ap,  g_attn);

    cudaFuncSetAttribute(gemm_h<float>,  cudaFuncAttributeMaxDynamicSharedMemorySize, SMEM_BYTES);
    cudaFuncSetAttribute(gemm_h<__half>, cudaFuncAttributeMaxDynamicSharedMemorySize, SMEM_BYTES);

    const dim3 blk(256);
    const long long CS = (long long)NSEQ * 2 * CTR;   // cat batch stride
    const long long PS = (long long)NSEQ * CTR;       // q/k/v batch stride
    const long long SS = (long long)NSEQ * NSEQ;      // sim/attn batch stride
    const long long XS = (long long)CH * NSEQ;        // out batch stride

    prep_weights<<<1280, blk>>>(Wq, Wk, Wv, Wo, wh);
    transpose_cn<<<dim3(NSEQ / 32, CH / 32, BATCH), dim3(32, 8)>>>(x, cat);

    // q[b][n][ct] = sum_c xT[n][c] * Wq[ct][c]
    const dim3 gq(CTR / BN, NSEQ / BM, BATCH);
    gemm_h<__half><<<gq, blk, SMEM_BYTES>>>(cat + 256, wh,         qp, CH, 2 * CTR, CH, CTR, CS, 0, PS, 1.0f);
    gemm_h<__half><<<gq, blk, SMEM_BYTES>>>(cat + 256, wh + 65536, kp, CH, 2 * CTR, CH, CTR, CS, 0, PS, 1.0f);

    // v[b][ct][n] = sum_c Wv[ct][c] * xT[n][c]
    const dim3 gv(NSEQ / BN, CTR / BM, BATCH);
    gemm_h<__half><<<gv, blk, SMEM_BYTES>>>(wh + 131072, cat + 256, vp, CH, CH, 2 * CTR, NSEQ, 0, CS, PS, 1.0f);

    // sim[b][n][m] = (1/16) sum_ct q[n][ct] * k[m][ct]  (f32 logits)
    const dim3 gsim(NSEQ / BN, NSEQ / BM, BATCH);
    gemm_h<float><<<gsim, blk, SMEM_BYTES>>>(qp, kp, sp, CTR, CTR, CTR, NSEQ, PS, PS, SS, 0.0625f);

    softmax_rows<<<dim3(NSEQ, BATCH), blk>>>(sp, ap);

    // ctx -> cat[b][n][0:256): sum_m attn[n][m] * v[ct][m]
    const dim3 gctx(CTR / BN, NSEQ / BM, BATCH);
    gemm_h<__half><<<gctx, blk, SMEM_BYTES>>>(ap, vp, cat, NSEQ, NSEQ, NSEQ, 2 * CTR, SS, PS, CS, 1.0f);

    // out[b][o][n] = sum_{k<512} Wo[o][k] * cat[n][k]
    const dim3 gout(NSEQ / BN, CH / BM, BATCH);
    gemm_h<float><<<gout, blk, SMEM_BYTES>>>(wh + 196608, cat, out, 2 * CTR, 2 * CTR, 2 * CTR, NSEQ, 0, CS, XS, 1.0f);
}